// round 2
// baseline (speedup 1.0000x reference)
#include <cuda_runtime.h>
#include <math.h>

// Problem constants
#define BATCH 4
#define SDIM  1024
#define HDIM  1024
#define NHEAD 16
#define DHEAD 64
#define FFDIM 4096
#define NTOK  4096   // BATCH*SDIM

// ---------------------------------------------------------------------------
// Scratch (allocation-free: __device__ globals)
// ---------------------------------------------------------------------------
__device__ float g_y1 [NTOK * HDIM];   // LN(x1)  -> k/v source
__device__ float g_y2 [NTOK * HDIM];   // LN(x2)  -> q source
__device__ float g_q  [NTOK * HDIM];
__device__ float g_k  [NTOK * HDIM];
__device__ float g_v  [NTOK * HDIM];
__device__ float g_o  [NTOK * HDIM];   // attention output (pre o-proj)
__device__ float g_x  [NTOK * HDIM];   // x2 + attn_out @ wo + bo
__device__ float g_yln[NTOK * HDIM];   // LN_f(g_x)
__device__ float g_h1 [NTOK * FFDIM];  // gelu(yln@w1+b1)

// ---------------------------------------------------------------------------
// LayerNorm: one block per row (1024 cols), 256 threads, float4 per thread
// ---------------------------------------------------------------------------
__global__ __launch_bounds__(256) void ln_kernel(
    const float* __restrict__ x, const float* __restrict__ g,
    const float* __restrict__ b, float* __restrict__ y)
{
    int row = blockIdx.x;
    int t   = threadIdx.x;
    float4 v = ((const float4*)(x + (size_t)row * HDIM))[t];
    float s  = v.x + v.y + v.z + v.w;
    float ss = v.x*v.x + v.y*v.y + v.z*v.z + v.w*v.w;
#pragma unroll
    for (int o = 16; o > 0; o >>= 1) {
        s  += __shfl_xor_sync(0xffffffffu, s,  o);
        ss += __shfl_xor_sync(0xffffffffu, ss, o);
    }
    __shared__ float sh[16];
    int w = t >> 5, lane = t & 31;
    if (lane == 0) { sh[w] = s; sh[8 + w] = ss; }
    __syncthreads();
    float S = 0.f, SS = 0.f;
#pragma unroll
    for (int i = 0; i < 8; i++) { S += sh[i]; SS += sh[8 + i]; }
    float mean = S * (1.0f / HDIM);
    float var  = SS * (1.0f / HDIM) - mean * mean;
    float inv  = rsqrtf(var + 1e-5f);
    float4 gg = ((const float4*)g)[t];
    float4 bb = ((const float4*)b)[t];
    float4 r;
    r.x = (v.x - mean) * inv * gg.x + bb.x;
    r.y = (v.y - mean) * inv * gg.y + bb.y;
    r.z = (v.z - mean) * inv * gg.z + bb.z;
    r.w = (v.w - mean) * inv * gg.w + bb.w;
    ((float4*)(y + (size_t)row * HDIM))[t] = r;
}

// ---------------------------------------------------------------------------
// Double-buffered tiled SIMT SGEMM: C[N,M] = A[N,K] @ W[K,M] + bias.
//   mode 0: none   (k, v projections)
//   mode 1: *0.125 (q projection; D^-0.5 applied after bias, as in reference)
//   mode 2: + R[N,M] residual (o-proj, ff2)
//   mode 3: exact GELU: v * normcdff(v)  (ff1)
// Tile: BM=BN=128, BK=16, 256 threads, 8x8 per thread (split 4+4 halves).
// Pipeline: LDG(next)->regs | compute(cur) | STS(next) | one barrier/step.
// All dims are multiples of 128 here, so no bounds checks.
// ---------------------------------------------------------------------------
__global__ __launch_bounds__(256) void gemm_kernel(
    const float* __restrict__ A, const float* __restrict__ W,
    const float* __restrict__ bias, const float* __restrict__ R,
    float* __restrict__ C, int N, int K, int M, int mode)
{
    __shared__ float As[2][16][132];   // A tile transposed: As[buf][k][m], padded
    __shared__ float Bs[2][16][128];   // W tile: Bs[buf][k][n]

    int tid = threadIdx.x;
    int bn  = blockIdx.x * 128;     // output col tile
    int bm  = blockIdx.y * 128;     // output row tile
    int tx  = tid & 15, ty = tid >> 4;

    // per-thread load coordinates (fixed across steps)
    int a_r0 = tid >> 2,            a_k0 = (tid & 3) << 2;           // phase 0
    int a_r1 = (256 + tid) >> 2,    a_k1 = ((256 + tid) & 3) << 2;   // phase 1 (same formula, idx+256)
    int b_k0 = tid >> 5,            b_c0 = (tid & 31) << 2;
    int b_k1 = (256 + tid) >> 5,    b_c1 = ((256 + tid) & 31) << 2;

    float acc[8][8];
#pragma unroll
    for (int i = 0; i < 8; i++)
#pragma unroll
        for (int j = 0; j < 8; j++) acc[i][j] = 0.f;

    // ---- preload tile 0 into buffer 0 ----
    {
        float4 a0 = *(const float4*)(A + (size_t)(bm + a_r0) * K + a_k0);
        float4 a1 = *(const float4*)(A + (size_t)(bm + a_r1) * K + a_k1);
        float4 w0 = *(const float4*)(W + (size_t)(b_k0) * M + bn + b_c0);
        float4 w1 = *(const float4*)(W + (size_t)(b_k1) * M + bn + b_c1);
        As[0][a_k0 + 0][a_r0] = a0.x; As[0][a_k0 + 1][a_r0] = a0.y;
        As[0][a_k0 + 2][a_r0] = a0.z; As[0][a_k0 + 3][a_r0] = a0.w;
        As[0][a_k1 + 0][a_r1] = a1.x; As[0][a_k1 + 1][a_r1] = a1.y;
        As[0][a_k1 + 2][a_r1] = a1.z; As[0][a_k1 + 3][a_r1] = a1.w;
        *(float4*)&Bs[0][b_k0][b_c0] = w0;
        *(float4*)&Bs[0][b_k1][b_c1] = w1;
    }
    __syncthreads();

    int nsteps = K >> 4;
    for (int step = 0; step < nsteps; step++) {
        int cur = step & 1;
        int nxt = cur ^ 1;
        int k0n = (step + 1) << 4;

        // issue next tile's global loads into registers (overlap with compute)
        float4 a0, a1, w0, w1;
        bool have_next = (step + 1 < nsteps);
        if (have_next) {
            a0 = *(const float4*)(A + (size_t)(bm + a_r0) * K + k0n + a_k0);
            a1 = *(const float4*)(A + (size_t)(bm + a_r1) * K + k0n + a_k1);
            w0 = *(const float4*)(W + (size_t)(k0n + b_k0) * M + bn + b_c0);
            w1 = *(const float4*)(W + (size_t)(k0n + b_k1) * M + bn + b_c1);
        }

        // compute current tile
#pragma unroll
        for (int kk = 0; kk < 16; kk++) {
            float a[8], bf[8];
            *(float4*)&a[0]  = *(float4*)&As[cur][kk][ty * 4];
            *(float4*)&a[4]  = *(float4*)&As[cur][kk][64 + ty * 4];
            *(float4*)&bf[0] = *(float4*)&Bs[cur][kk][tx * 4];
            *(float4*)&bf[4] = *(float4*)&Bs[cur][kk][64 + tx * 4];
#pragma unroll
            for (int i = 0; i < 8; i++)
#pragma unroll
                for (int j = 0; j < 8; j++)
                    acc[i][j] += a[i] * bf[j];
        }

        // store next tile into the other buffer
        if (have_next) {
            As[nxt][a_k0 + 0][a_r0] = a0.x; As[nxt][a_k0 + 1][a_r0] = a0.y;
            As[nxt][a_k0 + 2][a_r0] = a0.z; As[nxt][a_k0 + 3][a_r0] = a0.w;
            As[nxt][a_k1 + 0][a_r1] = a1.x; As[nxt][a_k1 + 1][a_r1] = a1.y;
            As[nxt][a_k1 + 2][a_r1] = a1.z; As[nxt][a_k1 + 3][a_r1] = a1.w;
            *(float4*)&Bs[nxt][b_k0][b_c0] = w0;
            *(float4*)&Bs[nxt][b_k1][b_c1] = w1;
        }
        __syncthreads();
    }

    // epilogue
#pragma unroll
    for (int i = 0; i < 8; i++) {
        int r = bm + (i < 4 ? ty * 4 + i : 64 + ty * 4 + (i - 4));
#pragma unroll
        for (int jh = 0; jh < 2; jh++) {
            int c = bn + (jh == 0 ? tx * 4 : 64 + tx * 4);
            float4 bi = *(const float4*)(bias + c);
            float vr[4];
            vr[0] = acc[i][jh * 4 + 0] + bi.x;
            vr[1] = acc[i][jh * 4 + 1] + bi.y;
            vr[2] = acc[i][jh * 4 + 2] + bi.z;
            vr[3] = acc[i][jh * 4 + 3] + bi.w;
            if (mode == 1) {
#pragma unroll
                for (int j = 0; j < 4; j++) vr[j] *= 0.125f;
            } else if (mode == 2) {
                float4 rr = *(const float4*)(R + (size_t)r * M + c);
                vr[0] += rr.x; vr[1] += rr.y; vr[2] += rr.z; vr[3] += rr.w;
            } else if (mode == 3) {
#pragma unroll
                for (int j = 0; j < 4; j++) vr[j] = vr[j] * normcdff(vr[j]);
            }
            float4 ov = make_float4(vr[0], vr[1], vr[2], vr[3]);
            *(float4*)(C + (size_t)r * M + c) = ov;
        }
    }
}

// ---------------------------------------------------------------------------
// Attention: flash-style with online softmax.
// grid (S/64, NH, B), 64 threads/block. Thread t owns q-row (qb+t).
// K/V streamed in chunks of 32 rows through smem. Bias streamed from gmem
// (per-lane contiguous 128B per chunk -> full-line utilization).
// q is pre-scaled by D^-0.5 (folded into the q projection epilogue).
// ---------------------------------------------------------------------------
__global__ __launch_bounds__(64, 8) void attn_kernel(
    const float* __restrict__ Q, const float* __restrict__ Kb,
    const float* __restrict__ V, const float* __restrict__ bias,
    float* __restrict__ O)
{
    __shared__ float qs[64][68];   // padded: conflict-free per-row float4 reads
    __shared__ float ks[32][64];
    __shared__ float vs[32][64];

    int t  = threadIdx.x;          // 0..63, owns one q row
    int qb = blockIdx.x << 6;
    int h  = blockIdx.y, b = blockIdx.z;

    // cooperative q tile load (64 x 64)
#pragma unroll
    for (int i = 0; i < 16; i++) {
        int f = i * 64 + t;
        int r = f >> 4, c = (f & 15) << 2;
        *(float4*)&qs[r][c] =
            *(const float4*)(Q + (size_t)(b * SDIM + qb + r) * HDIM + h * DHEAD + c);
    }

    const float* brow = bias + ((size_t)(b * NHEAD + h) * SDIM + qb + t) * SDIM;

    float m = -1e30f, l = 0.f;
    float o[64];
#pragma unroll
    for (int d = 0; d < 64; d++) o[d] = 0.f;

    for (int ch = 0; ch < 32; ch++) {
        int c0 = ch * 32;
        __syncthreads();   // previous chunk's compute done before overwrite
#pragma unroll
        for (int i = 0; i < 8; i++) {
            int f = i * 64 + t;
            int r = f >> 4, c = (f & 15) << 2;
            *(float4*)&ks[r][c] =
                *(const float4*)(Kb + (size_t)(b * SDIM + c0 + r) * HDIM + h * DHEAD + c);
            *(float4*)&vs[r][c] =
                *(const float4*)(V + (size_t)(b * SDIM + c0 + r) * HDIM + h * DHEAD + c);
        }
        __syncthreads();

        // bias slice for this thread's q row: 32 contiguous floats via float4
        float bsc[32];
#pragma unroll
        for (int i = 0; i < 8; i++) {
            float4 bv = *(const float4*)(brow + c0 + i * 4);
            bsc[i * 4 + 0] = bv.x; bsc[i * 4 + 1] = bv.y;
            bsc[i * 4 + 2] = bv.z; bsc[i * 4 + 3] = bv.w;
        }

        // scores s[kk] = q_row . k_kk + bias
        float s[32];
#pragma unroll
        for (int kk = 0; kk < 32; kk++) {
            float acc = bsc[kk];
#pragma unroll
            for (int d = 0; d < 64; d += 4) {
                float4 qv = *(float4*)&qs[t][d];
                float4 kv = *(float4*)&ks[kk][d];
                acc += qv.x * kv.x + qv.y * kv.y + qv.z * kv.z + qv.w * kv.w;
            }
            s[kk] = acc;
        }

        // online softmax update
        float mx = m;
#pragma unroll
        for (int kk = 0; kk < 32; kk++) mx = fmaxf(mx, s[kk]);
        float corr = __expf(m - mx);
        m = mx;
        l *= corr;
#pragma unroll
        for (int kk = 0; kk < 32; kk++) { s[kk] = __expf(s[kk] - mx); l += s[kk]; }
#pragma unroll
        for (int d = 0; d < 64; d++) o[d] *= corr;
#pragma unroll
        for (int kk = 0; kk < 32; kk++) {
            float p = s[kk];
#pragma unroll
            for (int d = 0; d < 64; d += 4) {
                float4 vv = *(float4*)&vs[kk][d];
                o[d + 0] += p * vv.x; o[d + 1] += p * vv.y;
                o[d + 2] += p * vv.z; o[d + 3] += p * vv.w;
            }
        }
    }

    float inv = 1.0f / l;
    float* orow = O + (size_t)(b * SDIM + qb + t) * HDIM + h * DHEAD;
#pragma unroll
    for (int d = 0; d < 64; d += 4) {
        float4 ov = make_float4(o[d] * inv, o[d + 1] * inv, o[d + 2] * inv, o[d + 3] * inv);
        *(float4*)(orow + d) = ov;
    }
}

// ---------------------------------------------------------------------------
// Launch sequence (graph-capturable: kernel launches only)
// ---------------------------------------------------------------------------
extern "C" void kernel_launch(void* const* d_in, const int* in_sizes, int n_in,
                              void* d_out, int out_size)
{
    const float* x1    = (const float*)d_in[0];
    const float* x2    = (const float*)d_in[1];
    const float* abias = (const float*)d_in[2];
    const float* ln1_g = (const float*)d_in[3];
    const float* ln1_b = (const float*)d_in[4];
    const float* ln2_g = (const float*)d_in[5];
    const float* ln2_b = (const float*)d_in[6];
    const float* wq    = (const float*)d_in[7];
    const float* bq    = (const float*)d_in[8];
    const float* wk    = (const float*)d_in[9];
    const float* bk    = (const float*)d_in[10];
    const float* wv    = (const float*)d_in[11];
    const float* bv    = (const float*)d_in[12];
    const float* wo    = (const float*)d_in[13];
    const float* bo    = (const float*)d_in[14];
    const float* lnf_g = (const float*)d_in[15];
    const float* lnf_b = (const float*)d_in[16];
    const float* w1    = (const float*)d_in[17];
    const float* b1    = (const float*)d_in[18];
    const float* w2    = (const float*)d_in[19];
    const float* b2    = (const float*)d_in[20];
    float* out = (float*)d_out;

    static float *p_y1 = nullptr, *p_y2, *p_q, *p_k, *p_v, *p_o, *p_x, *p_yln, *p_h1;
    if (!p_y1) {
        cudaGetSymbolAddress((void**)&p_y1,  g_y1);
        cudaGetSymbolAddress((void**)&p_y2,  g_y2);
        cudaGetSymbolAddress((void**)&p_q,   g_q);
        cudaGetSymbolAddress((void**)&p_k,   g_k);
        cudaGetSymbolAddress((void**)&p_v,   g_v);
        cudaGetSymbolAddress((void**)&p_o,   g_o);
        cudaGetSymbolAddress((void**)&p_x,   g_x);
        cudaGetSymbolAddress((void**)&p_yln, g_yln);
        cudaGetSymbolAddress((void**)&p_h1,  g_h1);
    }

    // 1) pre-LN for both streams
    ln_kernel<<<NTOK, 256>>>(x1, ln1_g, ln1_b, p_y1);
    ln_kernel<<<NTOK, 256>>>(x2, ln2_g, ln2_b, p_y2);

    // 2) q/k/v projections (q fused with D^-0.5 scale)
    dim3 gproj(HDIM / 128, NTOK / 128);
    gemm_kernel<<<gproj, 256>>>(p_y2, wq, bq, nullptr, p_q, NTOK, HDIM, HDIM, 1);
    gemm_kernel<<<gproj, 256>>>(p_y1, wk, bk, nullptr, p_k, NTOK, HDIM, HDIM, 0);
    gemm_kernel<<<gproj, 256>>>(p_y1, wv, bv, nullptr, p_v, NTOK, HDIM, HDIM, 0);

    // 3) attention with bias + softmax (flash-style)
    attn_kernel<<<dim3(SDIM / 64, NHEAD, BATCH), 64>>>(p_q, p_k, p_v, abias, p_o);

    // 4) output projection + residual: x = x2 + o@wo + bo
    gemm_kernel<<<gproj, 256>>>(p_o, wo, bo, x2, p_x, NTOK, HDIM, HDIM, 2);

    // 5) final LN
    ln_kernel<<<NTOK, 256>>>(p_x, lnf_g, lnf_b, p_yln);

    // 6) FFN: h1 = gelu(yln@w1+b1);  out = x + h1@w2 + b2
    gemm_kernel<<<dim3(FFDIM / 128, NTOK / 128), 256>>>(p_yln, w1, b1, nullptr, p_h1,
                                                        NTOK, HDIM, FFDIM, 3);
    gemm_kernel<<<dim3(HDIM / 128, NTOK / 128), 256>>>(p_h1, w2, b2, p_x, out,
                                                       NTOK, FFDIM, HDIM, 2);
}

// round 17
// speedup vs baseline: 1.5485x; 1.5485x over previous
#include <cuda_runtime.h>
#include <cuda_bf16.h>
#include <math.h>
#include <cstdint>

// Problem constants
#define BATCH 4
#define SDIM  1024
#define HDIM  1024
#define NHEAD 16
#define DHEAD 64
#define FFDIM 4096
#define NTOK  4096   // BATCH*SDIM

// ===========================================================================
// mma.sync helpers (sm_80+ features only -- no 'a'-suffix arch gating)
// ===========================================================================
__device__ __forceinline__ uint32_t smem_to_u32(const void* p) {
    uint32_t a;
    asm("{ .reg .u64 t; cvta.to.shared.u64 t, %1; cvt.u32.u64 %0, t; }"
        : "=r"(a) : "l"(p));
    return a;
}
__device__ __forceinline__ void ldsm_x4(uint32_t addr, uint32_t* r) {
    asm volatile("ldmatrix.sync.aligned.m8n8.x4.shared.b16 {%0,%1,%2,%3}, [%4];"
        : "=r"(r[0]), "=r"(r[1]), "=r"(r[2]), "=r"(r[3]) : "r"(addr));
}
__device__ __forceinline__ void mma16816(float* d, const uint32_t* a,
                                         uint32_t b0, uint32_t b1) {
    asm volatile(
        "mma.sync.aligned.m16n8k16.row.col.f32.bf16.bf16.f32 "
        "{%0,%1,%2,%3}, {%4,%5,%6,%7}, {%8,%9}, {%0,%1,%2,%3};"
        : "+f"(d[0]), "+f"(d[1]), "+f"(d[2]), "+f"(d[3])
        : "r"(a[0]), "r"(a[1]), "r"(a[2]), "r"(a[3]), "r"(b0), "r"(b1));
}

// ===========================================================================
// Scratch (allocation-free: __device__ globals)
// ===========================================================================
__device__ __nv_bfloat16 g_y1h[NTOK * HDIM],  g_y1l[NTOK * HDIM];
__device__ __nv_bfloat16 g_y2h[NTOK * HDIM],  g_y2l[NTOK * HDIM];
__device__ float         g_q  [NTOK * HDIM];
__device__ float         g_k  [NTOK * HDIM];
__device__ float         g_v  [NTOK * HDIM];
__device__ __nv_bfloat16 g_oh [NTOK * HDIM],  g_ol [NTOK * HDIM];
__device__ float         g_x  [NTOK * HDIM];
__device__ __nv_bfloat16 g_ylnh[NTOK * HDIM], g_ylnl[NTOK * HDIM];
__device__ __nv_bfloat16 g_h1h[NTOK * FFDIM], g_h1l[NTOK * FFDIM];
// Transposed + split weights: [M x K] bf16
__device__ __nv_bfloat16 g_wqTh[HDIM * HDIM], g_wqTl[HDIM * HDIM];
__device__ __nv_bfloat16 g_wkTh[HDIM * HDIM], g_wkTl[HDIM * HDIM];
__device__ __nv_bfloat16 g_wvTh[HDIM * HDIM], g_wvTl[HDIM * HDIM];
__device__ __nv_bfloat16 g_woTh[HDIM * HDIM], g_woTl[HDIM * HDIM];
__device__ __nv_bfloat16 g_w1Th[FFDIM * HDIM], g_w1Tl[FFDIM * HDIM];
__device__ __nv_bfloat16 g_w2Th[HDIM * FFDIM], g_w2Tl[HDIM * FFDIM];

__device__ __forceinline__ void split_bf16(float x, __nv_bfloat16& h, __nv_bfloat16& l) {
    h = __float2bfloat16(x);
    l = __float2bfloat16(x - __bfloat162float(h));
}

// ===========================================================================
// Weight transpose + hi/lo split: W[K x M] fp32 -> Th/Tl[M x K] bf16
// ===========================================================================
__global__ __launch_bounds__(256) void convT_kernel(
    const float* __restrict__ W, __nv_bfloat16* __restrict__ Th,
    __nv_bfloat16* __restrict__ Tl, int K, int M)
{
    __shared__ float ts[32][33];
    int m0 = blockIdx.x * 32, k0 = blockIdx.y * 32;
    int r = threadIdx.x >> 5, c = threadIdx.x & 31;
#pragma unroll
    for (int i = 0; i < 4; i++)
        ts[r + 8 * i][c] = W[(size_t)(k0 + r + 8 * i) * M + m0 + c];
    __syncthreads();
#pragma unroll
    for (int i = 0; i < 4; i++) {
        float v = ts[c][r + 8 * i];
        __nv_bfloat16 h, l; split_bf16(v, h, l);
        Th[(size_t)(m0 + r + 8 * i) * K + k0 + c] = h;
        Tl[(size_t)(m0 + r + 8 * i) * K + k0 + c] = l;
    }
}

// ===========================================================================
// LayerNorm -> bf16 hi/lo. One block per row, 256 threads, float4/thread.
// ===========================================================================
__global__ __launch_bounds__(256) void ln_bf16_kernel(
    const float* __restrict__ x, const float* __restrict__ g,
    const float* __restrict__ b, __nv_bfloat16* __restrict__ yh,
    __nv_bfloat16* __restrict__ yl)
{
    int row = blockIdx.x;
    int t   = threadIdx.x;
    float4 v = ((const float4*)(x + (size_t)row * HDIM))[t];
    float s  = v.x + v.y + v.z + v.w;
    float ss = v.x*v.x + v.y*v.y + v.z*v.z + v.w*v.w;
#pragma unroll
    for (int o = 16; o > 0; o >>= 1) {
        s  += __shfl_xor_sync(0xffffffffu, s,  o);
        ss += __shfl_xor_sync(0xffffffffu, ss, o);
    }
    __shared__ float sh[16];
    int w = t >> 5, lane = t & 31;
    if (lane == 0) { sh[w] = s; sh[8 + w] = ss; }
    __syncthreads();
    float S = 0.f, SS = 0.f;
#pragma unroll
    for (int i = 0; i < 8; i++) { S += sh[i]; SS += sh[8 + i]; }
    float mean = S * (1.0f / HDIM);
    float var  = SS * (1.0f / HDIM) - mean * mean;
    float inv  = rsqrtf(var + 1e-5f);
    float4 gg = ((const float4*)g)[t];
    float4 bb = ((const float4*)b)[t];
    float rv[4];
    rv[0] = (v.x - mean) * inv * gg.x + bb.x;
    rv[1] = (v.y - mean) * inv * gg.y + bb.y;
    rv[2] = (v.z - mean) * inv * gg.z + bb.z;
    rv[3] = (v.w - mean) * inv * gg.w + bb.w;
    __nv_bfloat16 hb[4], lb[4];
#pragma unroll
    for (int i = 0; i < 4; i++) split_bf16(rv[i], hb[i], lb[i]);
    *(uint2*)(yh + (size_t)row * HDIM + t * 4) = *(uint2*)hb;
    *(uint2*)(yl + (size_t)row * HDIM + t * 4) = *(uint2*)lb;
}

// ===========================================================================
// mma.sync GEMM: C[N,M] = A[N,K] @ B^T  where B arrays are [M x K] bf16.
// Hi/lo compensated: D = Ah*Bh + Ah*Bl + Al*Bh  (fp32 accum in registers).
// Tile 128x128, BK=32, 256 threads = 8 warps (4m x 2n), warp tile 32x64.
// smem rows padded to 80B -> conflict-free ldmatrix. Double-buffered.
//   mode 0: +bias -> fp32     mode 1: (+bias)*0.125 -> fp32
//   mode 2: +bias+R -> fp32   mode 3: gelu -> bf16 hi/lo (Ch/Cl)
// ===========================================================================
#define RSTRIDE_B 80                     // bytes per smem row (32 bf16 + pad)
#define TILE_SB  (128 * RSTRIDE_B)       // 10240 B per tile
#define STAGE_SB (4 * TILE_SB)           // 40960 B (Ah,Al,Bh,Bl)
#define DSMEM_SB (2 * STAGE_SB)          // 81920 B

__global__ __launch_bounds__(256, 1) void mma_gemm(
    const __nv_bfloat16* __restrict__ Ah, const __nv_bfloat16* __restrict__ Al,
    const __nv_bfloat16* __restrict__ Bh, const __nv_bfloat16* __restrict__ Bl,
    const float* __restrict__ bias, const float* __restrict__ R,
    float* __restrict__ C, __nv_bfloat16* __restrict__ Ch,
    __nv_bfloat16* __restrict__ Cl, int N, int K, int M, int mode)
{
    extern __shared__ char dsm[];
    const uint32_t smbase = smem_to_u32(dsm);

    int tid  = threadIdx.x;
    int wid  = tid >> 5, lane = tid & 31;
    int bn   = blockIdx.x * 128;     // output col tile (B rows)
    int bm   = blockIdx.y * 128;     // output row tile (A rows)
    int wr   = wid & 3;              // warp m index (4)
    int wc   = wid >> 2;             // warp n index (2)

    // ---- global->smem load geometry: thread covers 32B of one row per tile
    int r0 = tid >> 1;               // row 0..127
    int s0 = (tid & 1) * 2;          // 16B-seg 0 or 2 (covers s0, s0+1)
    size_t aoff = (size_t)(bm + r0) * K + s0 * 8;
    size_t boff = (size_t)(bn + r0) * K + s0 * 8;
    uint32_t st = (uint32_t)r0 * RSTRIDE_B + s0 * 16;

    // ---- ldmatrix lane addressing
    int a_r = lane & 15;
    int a_c = (lane >> 4) * 8;                       // +ks*16
    int b_r = (lane & 7) + ((lane >> 4) << 3);
    int b_c = ((lane >> 3) & 1) * 8;                 // +ks*16

    float acc[2][8][4];
#pragma unroll
    for (int mt = 0; mt < 2; mt++)
#pragma unroll
        for (int j = 0; j < 8; j++)
#pragma unroll
            for (int v = 0; v < 4; v++) acc[mt][j][v] = 0.f;

    // ---- preload stage 0
    {
        char* sb = dsm;
        *(uint4*)(sb + 0*TILE_SB + st)      = *(const uint4*)(Ah + aoff);
        *(uint4*)(sb + 0*TILE_SB + st + 16) = *(const uint4*)(Ah + aoff + 8);
        *(uint4*)(sb + 1*TILE_SB + st)      = *(const uint4*)(Al + aoff);
        *(uint4*)(sb + 1*TILE_SB + st + 16) = *(const uint4*)(Al + aoff + 8);
        *(uint4*)(sb + 2*TILE_SB + st)      = *(const uint4*)(Bh + boff);
        *(uint4*)(sb + 2*TILE_SB + st + 16) = *(const uint4*)(Bh + boff + 8);
        *(uint4*)(sb + 3*TILE_SB + st)      = *(const uint4*)(Bl + boff);
        *(uint4*)(sb + 3*TILE_SB + st + 16) = *(const uint4*)(Bl + boff + 8);
    }
    __syncthreads();

    int nsteps = K >> 5;     // BK=32
    for (int step = 0; step < nsteps; step++) {
        int cur = step & 1, nxt = cur ^ 1;
        bool have_next = (step + 1) < nsteps;
        int k0n = (step + 1) << 5;

        // issue next stage's global loads into registers
        uint4 vah0, vah1, val0, val1, vbh0, vbh1, vbl0, vbl1;
        if (have_next) {
            vah0 = *(const uint4*)(Ah + aoff + k0n);
            vah1 = *(const uint4*)(Ah + aoff + k0n + 8);
            val0 = *(const uint4*)(Al + aoff + k0n);
            val1 = *(const uint4*)(Al + aoff + k0n + 8);
            vbh0 = *(const uint4*)(Bh + boff + k0n);
            vbh1 = *(const uint4*)(Bh + boff + k0n + 8);
            vbl0 = *(const uint4*)(Bl + boff + k0n);
            vbl1 = *(const uint4*)(Bl + boff + k0n + 8);
        }

        // compute current stage: 2 k16 steps x 3 products
        uint32_t base = smbase + cur * STAGE_SB;
#pragma unroll
        for (int ks = 0; ks < 2; ks++) {
            uint32_t ahf[2][4], alf[2][4], bhf[4][4], blf[4][4];
#pragma unroll
            for (int mt = 0; mt < 2; mt++) {
                uint32_t ar = base + 0*TILE_SB
                    + (uint32_t)(wr*32 + mt*16 + a_r) * RSTRIDE_B + (ks*16 + a_c) * 2;
                ldsm_x4(ar, ahf[mt]);
                ldsm_x4(ar + TILE_SB, alf[mt]);      // Al tile at +TILE_SB
            }
#pragma unroll
            for (int nt = 0; nt < 4; nt++) {
                uint32_t br = base + 2*TILE_SB
                    + (uint32_t)(wc*64 + nt*16 + b_r) * RSTRIDE_B + (ks*16 + b_c) * 2;
                ldsm_x4(br, bhf[nt]);
                ldsm_x4(br + TILE_SB, blf[nt]);      // Bl tile at +TILE_SB
            }
#pragma unroll
            for (int mt = 0; mt < 2; mt++)
#pragma unroll
                for (int nt = 0; nt < 4; nt++)
#pragma unroll
                    for (int h = 0; h < 2; h++) {
                        float* d = acc[mt][nt*2 + h];
                        mma16816(d, ahf[mt], bhf[nt][2*h], bhf[nt][2*h+1]);
                        mma16816(d, ahf[mt], blf[nt][2*h], blf[nt][2*h+1]);
                        mma16816(d, alf[mt], bhf[nt][2*h], bhf[nt][2*h+1]);
                    }
        }

        // store next stage (different buffer; barrier orders vs next compute)
        if (have_next) {
            char* sb = dsm + nxt * STAGE_SB;
            *(uint4*)(sb + 0*TILE_SB + st)      = vah0;
            *(uint4*)(sb + 0*TILE_SB + st + 16) = vah1;
            *(uint4*)(sb + 1*TILE_SB + st)      = val0;
            *(uint4*)(sb + 1*TILE_SB + st + 16) = val1;
            *(uint4*)(sb + 2*TILE_SB + st)      = vbh0;
            *(uint4*)(sb + 2*TILE_SB + st + 16) = vbh1;
            *(uint4*)(sb + 3*TILE_SB + st)      = vbl0;
            *(uint4*)(sb + 3*TILE_SB + st + 16) = vbl1;
        }
        __syncthreads();
    }

    // ---- epilogue
    int g = lane >> 2, tig = lane & 3;
#pragma unroll
    for (int mt = 0; mt < 2; mt++) {
        int row0 = bm + wr*32 + mt*16 + g;        // rows row0, row0+8
#pragma unroll
        for (int j = 0; j < 8; j++) {
            int col = bn + wc*64 + j*8 + tig*2;
            float2 bi = *(const float2*)(bias + col);
            float v0 = acc[mt][j][0] + bi.x;
            float v1 = acc[mt][j][1] + bi.y;
            float v2 = acc[mt][j][2] + bi.x;
            float v3 = acc[mt][j][3] + bi.y;
            if (mode == 1) {
                v0 *= 0.125f; v1 *= 0.125f; v2 *= 0.125f; v3 *= 0.125f;
            } else if (mode == 2) {
                float2 ra = *(const float2*)(R + (size_t)row0 * M + col);
                float2 rb = *(const float2*)(R + (size_t)(row0 + 8) * M + col);
                v0 += ra.x; v1 += ra.y; v2 += rb.x; v3 += rb.y;
            } else if (mode == 3) {
                v0 = v0 * normcdff(v0); v1 = v1 * normcdff(v1);
                v2 = v2 * normcdff(v2); v3 = v3 * normcdff(v3);
            }
            if (mode == 3) {
                __nv_bfloat16 h0, l0, h1, l1, h2, l2, h3, l3;
                split_bf16(v0, h0, l0); split_bf16(v1, h1, l1);
                split_bf16(v2, h2, l2); split_bf16(v3, h3, l3);
                __nv_bfloat162 ph0; ph0.x = h0; ph0.y = h1;
                __nv_bfloat162 pl0; pl0.x = l0; pl0.y = l1;
                __nv_bfloat162 ph1; ph1.x = h2; ph1.y = h3;
                __nv_bfloat162 pl1; pl1.x = l2; pl1.y = l3;
                *(__nv_bfloat162*)(Ch + (size_t)row0 * M + col)       = ph0;
                *(__nv_bfloat162*)(Cl + (size_t)row0 * M + col)       = pl0;
                *(__nv_bfloat162*)(Ch + (size_t)(row0 + 8) * M + col) = ph1;
                *(__nv_bfloat162*)(Cl + (size_t)(row0 + 8) * M + col) = pl1;
            } else {
                *(float2*)(C + (size_t)row0 * M + col)       = make_float2(v0, v1);
                *(float2*)(C + (size_t)(row0 + 8) * M + col) = make_float2(v2, v3);
            }
        }
    }
}

// ===========================================================================
// Attention: flash-style, fp32, writes bf16 hi/lo output directly.
// grid (S/64, NH, B), 64 threads/block; thread t owns q-row qb+t.
// ===========================================================================
__global__ __launch_bounds__(64, 8) void attn_kernel(
    const float* __restrict__ Q, const float* __restrict__ Kb,
    const float* __restrict__ V, const float* __restrict__ bias,
    __nv_bfloat16* __restrict__ Oh, __nv_bfloat16* __restrict__ Ol)
{
    __shared__ float qs[64][68];
    __shared__ float ks[32][64];
    __shared__ float vs[32][64];

    int t  = threadIdx.x;
    int qb = blockIdx.x << 6;
    int h  = blockIdx.y, b = blockIdx.z;

#pragma unroll
    for (int i = 0; i < 16; i++) {
        int f = i * 64 + t;
        int r = f >> 4, c = (f & 15) << 2;
        *(float4*)&qs[r][c] =
            *(const float4*)(Q + (size_t)(b * SDIM + qb + r) * HDIM + h * DHEAD + c);
    }

    const float* brow = bias + ((size_t)(b * NHEAD + h) * SDIM + qb + t) * SDIM;

    float m = -1e30f, l = 0.f;
    float o[64];
#pragma unroll
    for (int d = 0; d < 64; d++) o[d] = 0.f;

    for (int ch = 0; ch < 32; ch++) {
        int c0 = ch * 32;
        __syncthreads();
#pragma unroll
        for (int i = 0; i < 8; i++) {
            int f = i * 64 + t;
            int r = f >> 4, c = (f & 15) << 2;
            *(float4*)&ks[r][c] =
                *(const float4*)(Kb + (size_t)(b * SDIM + c0 + r) * HDIM + h * DHEAD + c);
            *(float4*)&vs[r][c] =
                *(const float4*)(V + (size_t)(b * SDIM + c0 + r) * HDIM + h * DHEAD + c);
        }
        __syncthreads();

        float bsc[32];
#pragma unroll
        for (int i = 0; i < 8; i++) {
            float4 bv = *(const float4*)(brow + c0 + i * 4);
            bsc[i * 4 + 0] = bv.x; bsc[i * 4 + 1] = bv.y;
            bsc[i * 4 + 2] = bv.z; bsc[i * 4 + 3] = bv.w;
        }

        float s[32];
#pragma unroll
        for (int kk = 0; kk < 32; kk++) {
            float acc = bsc[kk];
#pragma unroll
            for (int d = 0; d < 64; d += 4) {
                float4 qv = *(float4*)&qs[t][d];
                float4 kv = *(float4*)&ks[kk][d];
                acc += qv.x * kv.x + qv.y * kv.y + qv.z * kv.z + qv.w * kv.w;
            }
            s[kk] = acc;
        }

        float mx = m;
#pragma unroll
        for (int kk = 0; kk < 32; kk++) mx = fmaxf(mx, s[kk]);
        float corr = __expf(m - mx);
        m = mx;
        l *= corr;
#pragma unroll
        for (int kk = 0; kk < 32; kk++) { s[kk] = __expf(s[kk] - mx); l += s[kk]; }
#pragma unroll
        for (int d = 0; d < 64; d++) o[d] *= corr;
#pragma unroll
        for (int kk = 0; kk < 32; kk++) {
            float p = s[kk];
#pragma unroll
            for (int d = 0; d < 64; d += 4) {
                float4 vv = *(float4*)&vs[kk][d];
                o[d + 0] += p * vv.x; o[d + 1] += p * vv.y;
                o[d + 2] += p * vv.z; o[d + 3] += p * vv.w;
            }
        }
    }

    float inv = 1.0f / l;
    __nv_bfloat16 hb[64], lb[64];
#pragma unroll
    for (int d = 0; d < 64; d++) {
        float v = o[d] * inv;
        split_bf16(v, hb[d], lb[d]);
    }
    size_t ofs = (size_t)(b * SDIM + qb + t) * HDIM + h * DHEAD;
    uint4* ph = (uint4*)(Oh + ofs);
    uint4* pl = (uint4*)(Ol + ofs);
#pragma unroll
    for (int i = 0; i < 8; i++) { ph[i] = ((uint4*)hb)[i]; pl[i] = ((uint4*)lb)[i]; }
}

// ===========================================================================
// Launch sequence
// ===========================================================================
extern "C" void kernel_launch(void* const* d_in, const int* in_sizes, int n_in,
                              void* d_out, int out_size)
{
    const float* x1    = (const float*)d_in[0];
    const float* x2    = (const float*)d_in[1];
    const float* abias = (const float*)d_in[2];
    const float* ln1_g = (const float*)d_in[3];
    const float* ln1_b = (const float*)d_in[4];
    const float* ln2_g = (const float*)d_in[5];
    const float* ln2_b = (const float*)d_in[6];
    const float* wq    = (const float*)d_in[7];
    const float* bq    = (const float*)d_in[8];
    const float* wk    = (const float*)d_in[9];
    const float* bk    = (const float*)d_in[10];
    const float* wv    = (const float*)d_in[11];
    const float* bv    = (const float*)d_in[12];
    const float* wo    = (const float*)d_in[13];
    const float* bo    = (const float*)d_in[14];
    const float* lnf_g = (const float*)d_in[15];
    const float* lnf_b = (const float*)d_in[16];
    const float* w1    = (const float*)d_in[17];
    const float* b1    = (const float*)d_in[18];
    const float* w2    = (const float*)d_in[19];
    const float* b2    = (const float*)d_in[20];
    float* out = (float*)d_out;

    struct Ptrs {
        __nv_bfloat16 *y1h,*y1l,*y2h,*y2l,*oh,*ol,*ylnh,*ylnl,*h1h,*h1l;
        __nv_bfloat16 *wqTh,*wqTl,*wkTh,*wkTl,*wvTh,*wvTl,*woTh,*woTl,*w1Th,*w1Tl,*w2Th,*w2Tl;
        float *q,*k,*v,*x;
    };
    static Ptrs P; static bool init = false;
    if (!init) {
        cudaGetSymbolAddress((void**)&P.y1h, g_y1h); cudaGetSymbolAddress((void**)&P.y1l, g_y1l);
        cudaGetSymbolAddress((void**)&P.y2h, g_y2h); cudaGetSymbolAddress((void**)&P.y2l, g_y2l);
        cudaGetSymbolAddress((void**)&P.oh,  g_oh);  cudaGetSymbolAddress((void**)&P.ol,  g_ol);
        cudaGetSymbolAddress((void**)&P.ylnh,g_ylnh);cudaGetSymbolAddress((void**)&P.ylnl,g_ylnl);
        cudaGetSymbolAddress((void**)&P.h1h, g_h1h); cudaGetSymbolAddress((void**)&P.h1l, g_h1l);
        cudaGetSymbolAddress((void**)&P.wqTh,g_wqTh);cudaGetSymbolAddress((void**)&P.wqTl,g_wqTl);
        cudaGetSymbolAddress((void**)&P.wkTh,g_wkTh);cudaGetSymbolAddress((void**)&P.wkTl,g_wkTl);
        cudaGetSymbolAddress((void**)&P.wvTh,g_wvTh);cudaGetSymbolAddress((void**)&P.wvTl,g_wvTl);
        cudaGetSymbolAddress((void**)&P.woTh,g_woTh);cudaGetSymbolAddress((void**)&P.woTl,g_woTl);
        cudaGetSymbolAddress((void**)&P.w1Th,g_w1Th);cudaGetSymbolAddress((void**)&P.w1Tl,g_w1Tl);
        cudaGetSymbolAddress((void**)&P.w2Th,g_w2Th);cudaGetSymbolAddress((void**)&P.w2Tl,g_w2Tl);
        cudaGetSymbolAddress((void**)&P.q, g_q); cudaGetSymbolAddress((void**)&P.k, g_k);
        cudaGetSymbolAddress((void**)&P.v, g_v); cudaGetSymbolAddress((void**)&P.x, g_x);
        cudaFuncSetAttribute(mma_gemm, cudaFuncAttributeMaxDynamicSharedMemorySize, DSMEM_SB);
        init = true;
    }

    // 0) weight transpose + split (per-launch)
    convT_kernel<<<dim3(HDIM/32,  HDIM/32),  256>>>(wq, P.wqTh, P.wqTl, HDIM, HDIM);
    convT_kernel<<<dim3(HDIM/32,  HDIM/32),  256>>>(wk, P.wkTh, P.wkTl, HDIM, HDIM);
    convT_kernel<<<dim3(HDIM/32,  HDIM/32),  256>>>(wv, P.wvTh, P.wvTl, HDIM, HDIM);
    convT_kernel<<<dim3(HDIM/32,  HDIM/32),  256>>>(wo, P.woTh, P.woTl, HDIM, HDIM);
    convT_kernel<<<dim3(FFDIM/32, HDIM/32),  256>>>(w1, P.w1Th, P.w1Tl, HDIM, FFDIM);
    convT_kernel<<<dim3(HDIM/32,  FFDIM/32), 256>>>(w2, P.w2Th, P.w2Tl, FFDIM, HDIM);

    // 1) pre-LN (fused bf16 hi/lo split)
    ln_bf16_kernel<<<NTOK, 256>>>(x1, ln1_g, ln1_b, P.y1h, P.y1l);
    ln_bf16_kernel<<<NTOK, 256>>>(x2, ln2_g, ln2_b, P.y2h, P.y2l);

    // 2) q/k/v projections (tensor cores via mma.sync; q fused with D^-0.5)
    dim3 gproj(HDIM / 128, NTOK / 128);
    mma_gemm<<<gproj, 256, DSMEM_SB>>>(P.y2h, P.y2l, P.wqTh, P.wqTl, bq, nullptr,
                                       P.q, nullptr, nullptr, NTOK, HDIM, HDIM, 1);
    mma_gemm<<<gproj, 256, DSMEM_SB>>>(P.y1h, P.y1l, P.wkTh, P.wkTl, bk, nullptr,
                                       P.k, nullptr, nullptr, NTOK, HDIM, HDIM, 0);
    mma_gemm<<<gproj, 256, DSMEM_SB>>>(P.y1h, P.y1l, P.wvTh, P.wvTl, bv, nullptr,
                                       P.v, nullptr, nullptr, NTOK, HDIM, HDIM, 0);

    // 3) attention (fp32 flash) -> bf16 hi/lo
    attn_kernel<<<dim3(SDIM / 64, NHEAD, BATCH), 64>>>(P.q, P.k, P.v, abias, P.oh, P.ol);

    // 4) o-proj + residual: x = x2 + o@wo + bo
    mma_gemm<<<gproj, 256, DSMEM_SB>>>(P.oh, P.ol, P.woTh, P.woTl, bo, x2,
                                       P.x, nullptr, nullptr, NTOK, HDIM, HDIM, 2);

    // 5) final LN -> bf16 hi/lo
    ln_bf16_kernel<<<NTOK, 256>>>(P.x, lnf_g, lnf_b, P.ylnh, P.ylnl);

    // 6) FFN
    mma_gemm<<<dim3(FFDIM / 128, NTOK / 128), 256, DSMEM_SB>>>(
        P.ylnh, P.ylnl, P.w1Th, P.w1Tl, b1, nullptr,
        nullptr, P.h1h, P.h1l, NTOK, HDIM, FFDIM, 3);
    mma_gemm<<<dim3(HDIM / 128, NTOK / 128), 256, DSMEM_SB>>>(
        P.h1h, P.h1l, P.w2Th, P.w2Tl, b2, P.x,
        out, nullptr, nullptr, NTOK, FFDIM, HDIM, 2);
}